// round 14
// baseline (speedup 1.0000x reference)
#include <cuda_runtime.h>
#include <cuda_fp16.h>
#include <cstdint>

#define N_NODES 50000
#define N_EDGES 800000
#define D_IN    16
#define HID     128
#define D_OUT   4
#define N_LAYERS 3
#define LN_EPS  1e-5f

#define SCAN_BLOCKS 196   // ceil(50000/256)

// Scratch (device globals: allocation-free, graph-capturable).
// g_cnt relies on static zero-init for the first call; every call re-zeroes it
// inside combo2 (fill phase), so all calls see zeros (deterministic).
__device__ float  g_h   [N_NODES * HID];   // fp32 residual stream
__device__ __half g_hnh [N_NODES * HID];   // fp16 LN output
__device__ __half g_aggh[N_NODES * HID];   // fp16 aggregate
__device__ __half g_Wh  [N_LAYERS * HID * 2 * HID];  // [l][n=128][k=256] fp16
__device__ float g_inv [N_NODES];
__device__ int   g_cnt [N_NODES];
__device__ int   g_off [N_NODES + 1];
__device__ int   g_cur [N_NODES];
__device__ int   g_bsum[SCAN_BLOCKS];
__device__ int   g_esrc[N_EDGES];

// ---------------------------------------------------------------------------
// fp16 mma.sync (base PTX): D += A(16x16) * B(16x8), fp32 accum
// ---------------------------------------------------------------------------
__device__ __forceinline__ void mma_fp16(float* c, const uint32_t* a, const uint32_t* b) {
    asm volatile(
        "mma.sync.aligned.m16n8k16.row.col.f32.f16.f16.f32 "
        "{%0,%1,%2,%3}, {%4,%5,%6,%7}, {%8,%9}, {%0,%1,%2,%3};"
        : "+f"(c[0]), "+f"(c[1]), "+f"(c[2]), "+f"(c[3])
        : "r"(a[0]), "r"(a[1]), "r"(a[2]), "r"(a[3]), "r"(b[0]), "r"(b[1]));
}

// ---------------------------------------------------------------------------
// Warp LN of one node row: read fp32 g_h, write fp16 g_hnh. 4 cols/lane.
// ---------------------------------------------------------------------------
__device__ __forceinline__ void ln_node(int node, int lane,
                                        const float* __restrict__ g,
                                        const float* __restrict__ b) {
    float4 v = ((const float4*)(g_h + (size_t)node * HID))[lane];
    float s = v.x + v.y + v.z + v.w;
#pragma unroll
    for (int o = 16; o; o >>= 1) s += __shfl_xor_sync(0xFFFFFFFFu, s, o);
    float mu = s * (1.0f / HID);
    float dx = v.x - mu, dy = v.y - mu, dz = v.z - mu, dw = v.w - mu;
    float q = dx * dx + dy * dy + dz * dz + dw * dw;
#pragma unroll
    for (int o = 16; o; o >>= 1) q += __shfl_xor_sync(0xFFFFFFFFu, q, o);
    float rs = rsqrtf(q * (1.0f / HID) + LN_EPS);
    int c = lane * 4;
    float4 gg = *(const float4*)(g + c);
    float4 bb = *(const float4*)(b + c);
    float ox = dx * rs * gg.x + bb.x;
    float oy = dy * rs * gg.y + bb.y;
    float oz = dz * rs * gg.z + bb.z;
    float ow = dw * rs * gg.w + bb.w;
    __half2 hh0 = __floats2half2_rn(ox, oy);
    __half2 hh1 = __floats2half2_rn(oz, ow);
    uint2 hp;
    hp.x = *(uint32_t*)&hh0;
    hp.y = *(uint32_t*)&hh1;
    ((uint2*)(g_hnh + (size_t)node * HID))[lane] = hp;
}

// ---------------------------------------------------------------------------
// combo1: [count blocks 0..3124] + [wprep 3125..3220] + [in_gemm 3221..6345]
// All independent work; 256 threads each.
// ---------------------------------------------------------------------------
#define C1_COUNT 3125
#define C1_WPREP 96
#define C1_INGEMM 3125
#define C1_GRID (C1_COUNT + C1_WPREP + C1_INGEMM)

__global__ void k_combo1(const int* __restrict__ dst,
                         const float* __restrict__ Wl, const float* __restrict__ Wr,
                         const float* __restrict__ x,
                         const float* __restrict__ Win, const float* __restrict__ bin,
                         const float* __restrict__ lng, const float* __restrict__ lnb) {
    __shared__ char smbuf[(16 * D_IN + D_IN * HID) * 4];  // 9KB, max of roles
    int b = blockIdx.x;
    int tid = threadIdx.x;

    if (b < C1_COUNT) {
        // ---- degree histogram ----
        int e = b * 256 + tid;
        if (e < N_EDGES) atomicAdd(&g_cnt[dst[e]], 1);
    } else if (b < C1_COUNT + C1_WPREP) {
        // ---- weight transpose to fp16 ----
        int wb = b - C1_COUNT;
        int K0 = (wb & 7) * 32;
        int N0 = ((wb >> 3) & 3) * 32;
        int l = wb >> 5;
        int tx = tid & 31, ty = tid >> 5;
        float (*s)[33] = (float(*)[33])smbuf;
        const float* WlL = Wl + l * HID * HID;
        const float* WrL = Wr + l * HID * HID;
#pragma unroll
        for (int i = 0; i < 4; i++) {
            int k = K0 + ty + i * 8;
            int n = N0 + tx;
            s[ty + i * 8][tx] = (k < HID) ? WlL[k * HID + n] : WrL[(k - HID) * HID + n];
        }
        __syncthreads();
        __half* O = g_Wh + (size_t)l * HID * 2 * HID;
#pragma unroll
        for (int i = 0; i < 4; i++) {
            int n = N0 + ty + i * 8;
            int k = K0 + tx;
            O[(size_t)n * 256 + k] = __float2half_rn(s[tx][ty + i * 8]);
        }
    } else {
        // ---- h = x @ W_in + b_in ----
        int gb = b - C1_COUNT - C1_WPREP;
        int m0 = gb * 16;
        float (*xs)[D_IN] = (float(*)[D_IN])smbuf;
        float (*Ws)[HID] = (float(*)[HID])(smbuf + 16 * D_IN * 4);
#pragma unroll
        for (int i = 0; i < 2; i++) {
            int idx = tid + i * 256;
            ((float4*)&Ws[0][0])[idx] = ((const float4*)Win)[idx];
        }
        {
            int r = tid >> 4, k = tid & 15;
            xs[r][k] = x[(size_t)(m0 + r) * D_IN + k];
        }
        __syncthreads();
        int col = tid & 127;
        int rh  = tid >> 7;
        float wc[D_IN];
#pragma unroll
        for (int k = 0; k < D_IN; k++) wc[k] = Ws[k][col];
        float bb = bin[col];
#pragma unroll
        for (int r = 0; r < 8; r++) {
            int row = rh * 8 + r;
            float acc = bb;
#pragma unroll
            for (int k = 0; k < D_IN; k++) acc += xs[row][k] * wc[k];
            g_h[(size_t)(m0 + row) * HID + col] = acc;
        }
    }
}

// ---------------------------------------------------------------------------
// scan1: per-256-chunk exclusive scan of counts
// ---------------------------------------------------------------------------
__global__ void k_scan1() {
    __shared__ int s[2][256];
    int b = blockIdx.x, t = threadIdx.x;
    int i = b * 256 + t;
    int v = (i < N_NODES) ? g_cnt[i] : 0;
    s[0][t] = v;
    __syncthreads();
    int p = 0;
#pragma unroll
    for (int off = 1; off < 256; off <<= 1) {
        int nv = s[p][t] + ((t >= off) ? s[p][t - off] : 0);
        s[p ^ 1][t] = nv;
        __syncthreads();
        p ^= 1;
    }
    if (i < N_NODES) g_off[i] = s[p][t] - v;
    if (t == 255) g_bsum[b] = s[p][255];
}

// scan2+scan3 fused: each block reduces bsum[0..b) itself.
__global__ void k_scan23() {
    __shared__ int red[256];
    int b = blockIdx.x, t = threadIdx.x;
    int v = (t < b) ? g_bsum[t] : 0;
    red[t] = v;
    __syncthreads();
#pragma unroll
    for (int off = 128; off; off >>= 1) {
        if (t < off) red[t] += red[t + off];
        __syncthreads();
    }
    int pre = red[0];
    int i = b * 256 + t;
    if (i < N_NODES) {
        int o = g_off[i] + pre;
        g_off[i] = o;
        g_cur[i] = o;
        g_inv[i] = 1.0f / fmaxf((float)g_cnt[i], 1.0f);
    }
    if (i == 0) g_off[N_NODES] = N_EDGES;
}

// ---------------------------------------------------------------------------
// combo2: [fill blocks 0..3124] + [LN layer-0 blocks 3125..9374]
// ---------------------------------------------------------------------------
#define C2_FILL 3125
#define C2_LN   6250
#define C2_GRID (C2_FILL + C2_LN)

__global__ void k_combo2(const int* __restrict__ src, const int* __restrict__ dst,
                         const float* __restrict__ lng, const float* __restrict__ lnb) {
    int b = blockIdx.x;
    int tid = threadIdx.x;
    if (b < C2_FILL) {
        int e = b * 256 + tid;
        if (e < N_EDGES) {
            int pos = atomicAdd(&g_cur[dst[e]], 1);
            g_esrc[pos] = src[e];
        }
        if (e < N_NODES) g_cnt[e] = 0;   // re-zero for next call
    } else {
        int node = ((b - C2_FILL) * 256 + tid) >> 5;
        int lane = tid & 31;
        if (node < N_NODES) ln_node(node, lane, lng, lnb);
    }
}

// ---------------------------------------------------------------------------
// Standalone LayerNorm (layers 1,2): one warp per node
// ---------------------------------------------------------------------------
__global__ void k_ln(const float* __restrict__ g, const float* __restrict__ b) {
    int node = (blockIdx.x * blockDim.x + threadIdx.x) >> 5;
    int lane = threadIdx.x & 31;
    if (node < N_NODES) ln_node(node, lane, g, b);
}

// ---------------------------------------------------------------------------
// Fused layer: [gather agg for own 128 rows] + [fp16 MMA GEMM + epilogue]
//   h = relu(h + [aggh | hnh] @ Wh + bl)
// Gather: 16 warps x 8 nodes, paired-edge scheme (lanes 0-15 edge 2j,
// lanes 16-31 edge 2j+1, uint4 = full 256B row), combine shfl_xor(16),
// write fp16 g_aggh. syncthreads. GEMM reads g_aggh back through L1.
// GEMM: CTA tile 128x128, K=256 in 16 chunks, 2-stage double buffer, 48B pitch.
// ---------------------------------------------------------------------------
#define LPITCH 48
#define STG    6144          // 128 rows * 48B
#define LAYER_SMEM (4 * STG) // A0,B0,A1,B1 = 24576

__global__ void __launch_bounds__(512) k_layer(int l, const float* __restrict__ bl) {
    extern __shared__ char sm[];
    int tid = threadIdx.x;
    int lane = tid & 31, wid = tid >> 5;
    int wm = wid & 3, wn = wid >> 2;
    int m0 = blockIdx.x * 128;

    // ---- Phase 0: gather agg for this CTA's rows ----
    {
        int half = lane >> 4;
        int hl = lane & 15;
        for (int i = 0; i < 8; i++) {
            int node = m0 + wid * 8 + i;
            if (node >= N_NODES) break;
            int beg = g_off[node];
            int end = g_off[node + 1];
            float4 a0 = make_float4(0.f, 0.f, 0.f, 0.f);
            float4 a1 = make_float4(0.f, 0.f, 0.f, 0.f);
            for (int e = beg; e < end; e += 32) {
                int rem = end - e;
                if (rem > 32) rem = 32;
                int sidx = (lane < rem) ? g_esrc[e + lane] : 0;
                int npair = rem >> 1;
#pragma unroll 4
                for (int j = 0; j < npair; j++) {
                    int s = __shfl_sync(0xFFFFFFFFu, sidx, 2 * j + half);
                    uint4 u = ((const uint4*)(g_hnh + (size_t)s * HID))[hl];
                    float2 f;
                    f = __half22float2(*(__half2*)&u.x); a0.x += f.x; a0.y += f.y;
                    f = __half22float2(*(__half2*)&u.y); a0.z += f.x; a0.w += f.y;
                    f = __half22float2(*(__half2*)&u.z); a1.x += f.x; a1.y += f.y;
                    f = __half22float2(*(__half2*)&u.w); a1.z += f.x; a1.w += f.y;
                }
                if (rem & 1) {
                    int s = __shfl_sync(0xFFFFFFFFu, sidx, rem - 1);
                    if (half == 0) {
                        uint4 u = ((const uint4*)(g_hnh + (size_t)s * HID))[hl];
                        float2 f;
                        f = __half22float2(*(__half2*)&u.x); a0.x += f.x; a0.y += f.y;
                        f = __half22float2(*(__half2*)&u.y); a0.z += f.x; a0.w += f.y;
                        f = __half22float2(*(__half2*)&u.z); a1.x += f.x; a1.y += f.y;
                        f = __half22float2(*(__half2*)&u.w); a1.z += f.x; a1.w += f.y;
                    }
                }
            }
            a0.x += __shfl_xor_sync(0xFFFFFFFFu, a0.x, 16);
            a0.y += __shfl_xor_sync(0xFFFFFFFFu, a0.y, 16);
            a0.z += __shfl_xor_sync(0xFFFFFFFFu, a0.z, 16);
            a0.w += __shfl_xor_sync(0xFFFFFFFFu, a0.w, 16);
            a1.x += __shfl_xor_sync(0xFFFFFFFFu, a1.x, 16);
            a1.y += __shfl_xor_sync(0xFFFFFFFFu, a1.y, 16);
            a1.z += __shfl_xor_sync(0xFFFFFFFFu, a1.z, 16);
            a1.w += __shfl_xor_sync(0xFFFFFFFFu, a1.w, 16);
            if (half == 0) {
                float inv = g_inv[node];
                __half2 h0 = __floats2half2_rn(a0.x * inv, a0.y * inv);
                __half2 h1 = __floats2half2_rn(a0.z * inv, a0.w * inv);
                __half2 h2 = __floats2half2_rn(a1.x * inv, a1.y * inv);
                __half2 h3 = __floats2half2_rn(a1.z * inv, a1.w * inv);
                uint4 o;
                o.x = *(uint32_t*)&h0; o.y = *(uint32_t*)&h1;
                o.z = *(uint32_t*)&h2; o.w = *(uint32_t*)&h3;
                ((uint4*)(g_aggh + (size_t)node * HID))[hl] = o;
            }
        }
    }
    __syncthreads();   // agg rows m0..m0+127 visible CTA-wide

    // ---- Phase 1: GEMM ----
    const __half* W_ = g_Wh + (size_t)l * HID * 2 * HID;

    float C[2][4][4];
#pragma unroll
    for (int mt = 0; mt < 2; mt++)
#pragma unroll
        for (int nt = 0; nt < 4; nt++)
#pragma unroll
            for (int j = 0; j < 4; j++) C[mt][nt][j] = 0.0f;

    int s_r = tid >> 2, s_q = tid & 3;
    int arow = m0 + s_r;
    if (arow >= N_NODES) arow = N_NODES - 1;

    uint2 av, bv;
    av = *(const uint2*)(g_aggh + (size_t)arow * HID + s_q * 4);
    bv = *(const uint2*)(W_ + (size_t)s_r * 256 + s_q * 4);

    for (int c = 0; c < 16; c++) {
        int st = c & 1;
        char* As = sm + st * 2 * STG;
        char* Bs = As + STG;

        *(uint2*)(As + s_r * LPITCH + s_q * 8) = av;
        *(uint2*)(Bs + s_r * LPITCH + s_q * 8) = bv;
        __syncthreads();

        if (c < 15) {
            int cn = c + 1;
            const __half* Asrc = (cn < 8) ? (g_aggh + cn * 16) : (g_hnh + (cn - 8) * 16);
            av = *(const uint2*)(Asrc + (size_t)arow * HID + s_q * 4);
            bv = *(const uint2*)(W_ + (size_t)s_r * 256 + cn * 16 + s_q * 4);
        }

        uint32_t a[2][4], b[4][2];
#pragma unroll
        for (int mt = 0; mt < 2; mt++) {
            int off = (wm * 32 + mt * 16 + (lane >> 2)) * LPITCH + (lane & 3) * 4;
            a[mt][0] = *(uint32_t*)(As + off);
            a[mt][1] = *(uint32_t*)(As + off + 8 * LPITCH);
            a[mt][2] = *(uint32_t*)(As + off + 16);
            a[mt][3] = *(uint32_t*)(As + off + 8 * LPITCH + 16);
        }
#pragma unroll
        for (int nt = 0; nt < 4; nt++) {
            int off = (wn * 32 + nt * 8 + (lane >> 2)) * LPITCH + (lane & 3) * 4;
            b[nt][0] = *(uint32_t*)(Bs + off);
            b[nt][1] = *(uint32_t*)(Bs + off + 16);
        }

#pragma unroll
        for (int mt = 0; mt < 2; mt++)
#pragma unroll
            for (int nt = 0; nt < 4; nt++)
                mma_fp16(C[mt][nt], a[mt], b[nt]);
        __syncthreads();
    }

    // Epilogue: residual + bias + relu into fp32 g_h
#pragma unroll
    for (int mt = 0; mt < 2; mt++) {
        int r0 = m0 + wm * 32 + mt * 16 + (lane >> 2);
#pragma unroll
        for (int half = 0; half < 2; half++) {
            int r = r0 + half * 8;
            if (r < N_NODES) {
#pragma unroll
                for (int nt = 0; nt < 4; nt++) {
                    int cb = wn * 32 + nt * 8 + (lane & 3) * 2;
                    float* hp = g_h + (size_t)r * HID + cb;
                    float2 h2 = *(float2*)hp;
                    float2 bb = *(const float2*)(bl + cb);
                    float2 o;
                    o.x = fmaxf(h2.x + C[mt][nt][half * 2 + 0] + bb.x, 0.0f);
                    o.y = fmaxf(h2.y + C[mt][nt][half * 2 + 1] + bb.y, 0.0f);
                    *(float2*)hp = o;
                }
            }
        }
    }
}

// ---------------------------------------------------------------------------
// out = h @ W_out + b_out   (50000 x 128 @ 128 x 4), one warp per node
// ---------------------------------------------------------------------------
__global__ void k_out(const float* __restrict__ Wo,
                      const float* __restrict__ bo,
                      float* __restrict__ out) {
    __shared__ float Ws[HID * D_OUT];
    int tid = threadIdx.x;
    for (int i = tid; i < HID * D_OUT; i += blockDim.x) Ws[i] = Wo[i];
    __syncthreads();

    int warp = (blockIdx.x * blockDim.x + tid) >> 5;
    int lane = tid & 31;
    if (warp >= N_NODES) return;

    const float* hr = g_h + (size_t)warp * HID;
    float a0 = 0.f, a1 = 0.f, a2 = 0.f, a3 = 0.f;
#pragma unroll
    for (int t = 0; t < 4; t++) {
        int k = lane + t * 32;
        float hv = hr[k];
        a0 += hv * Ws[k * D_OUT + 0];
        a1 += hv * Ws[k * D_OUT + 1];
        a2 += hv * Ws[k * D_OUT + 2];
        a3 += hv * Ws[k * D_OUT + 3];
    }
#pragma unroll
    for (int o = 16; o; o >>= 1) {
        a0 += __shfl_xor_sync(0xFFFFFFFFu, a0, o);
        a1 += __shfl_xor_sync(0xFFFFFFFFu, a1, o);
        a2 += __shfl_xor_sync(0xFFFFFFFFu, a2, o);
        a3 += __shfl_xor_sync(0xFFFFFFFFu, a3, o);
    }
    if (lane == 0) {
        float4 r;
        r.x = a0 + bo[0];
        r.y = a1 + bo[1];
        r.z = a2 + bo[2];
        r.w = a3 + bo[3];
        *(float4*)(out + (size_t)warp * D_OUT) = r;
    }
}

// ---------------------------------------------------------------------------
extern "C" void kernel_launch(void* const* d_in, const int* in_sizes, int n_in,
                              void* d_out, int out_size) {
    const float* x     = (const float*)d_in[0];
    const int*   ei    = (const int*)  d_in[1];
    const float* W_in  = (const float*)d_in[2];
    const float* b_in  = (const float*)d_in[3];
    const float* Wl    = (const float*)d_in[4];
    const float* bl    = (const float*)d_in[5];
    const float* Wr    = (const float*)d_in[6];
    const float* ln_g  = (const float*)d_in[7];
    const float* ln_b  = (const float*)d_in[8];
    const float* W_out = (const float*)d_in[9];
    const float* b_out = (const float*)d_in[10];
    float* out = (float*)d_out;

    const int* src = ei;             // edge_index[0]
    const int* dst = ei + N_EDGES;   // edge_index[1]

    cudaFuncSetAttribute(k_layer, cudaFuncAttributeMaxDynamicSharedMemorySize, LAYER_SMEM);

    // combo1: degree count + weight prep + input GEMM (independent)
    k_combo1<<<C1_GRID, 256>>>(dst, Wl, Wr, x, W_in, b_in, ln_g, ln_b);
    k_scan1<<<SCAN_BLOCKS, 256>>>();
    k_scan23<<<SCAN_BLOCKS, 256>>>();
    // combo2: CSR fill + LN(layer 0)
    k_combo2<<<C2_GRID, 256>>>(src, dst, ln_g, ln_b);

    for (int l = 0; l < N_LAYERS; l++) {
        k_layer<<<(N_NODES + 127) / 128, 512, LAYER_SMEM>>>(l, bl + l * HID);
        if (l + 1 < N_LAYERS)
            k_ln<<<(N_NODES * 32 + 255) / 256, 256>>>(ln_g + (l + 1) * HID,
                                                      ln_b + (l + 1) * HID);
    }

    k_out<<<(N_NODES * 32 + 255) / 256, 256>>>(W_out, b_out, out);
}

// round 15
// speedup vs baseline: 1.0698x; 1.0698x over previous
#include <cuda_runtime.h>
#include <cuda_fp16.h>
#include <cstdint>

#define N_NODES 50000
#define N_EDGES 800000
#define D_IN    16
#define HID     128
#define D_OUT   4
#define N_LAYERS 3
#define LN_EPS  1e-5f

#define SCAN_BLOCKS 196   // ceil(50000/256)

// Scratch (device globals: allocation-free, graph-capturable).
// g_cnt relies on static zero-init for the first call; every call re-zeroes it
// at the end of k_fill, so all calls see zeros (deterministic across replays).
__device__ float  g_h   [N_NODES * HID];   // fp32 residual stream
__device__ __half g_hnh [N_NODES * HID];   // fp16 LN output
__device__ __half g_aggh[N_NODES * HID];   // fp16 aggregate
__device__ __half g_Wh  [N_LAYERS * HID * 2 * HID];  // [l][n=128][k=256] fp16
__device__ float g_inv [N_NODES];
__device__ int   g_cnt [N_NODES];
__device__ int   g_off [N_NODES + 1];
__device__ int   g_cur [N_NODES];
__device__ int   g_bsum[SCAN_BLOCKS];
__device__ int   g_esrc[N_EDGES];

// ---------------------------------------------------------------------------
// fp16 mma.sync (base PTX): D += A(16x16) * B(16x8), fp32 accum
// ---------------------------------------------------------------------------
__device__ __forceinline__ void mma_fp16(float* c, const uint32_t* a, const uint32_t* b) {
    asm volatile(
        "mma.sync.aligned.m16n8k16.row.col.f32.f16.f16.f32 "
        "{%0,%1,%2,%3}, {%4,%5,%6,%7}, {%8,%9}, {%0,%1,%2,%3};"
        : "+f"(c[0]), "+f"(c[1]), "+f"(c[2]), "+f"(c[3])
        : "r"(a[0]), "r"(a[1]), "r"(a[2]), "r"(a[3]), "r"(b[0]), "r"(b[1]));
}

// ---------------------------------------------------------------------------
// CSR build (4 launches): count -> scan1 -> scan23 -> fill(+rezero)
// ---------------------------------------------------------------------------
__global__ void k_count(const int* __restrict__ dst) {
    int e = blockIdx.x * blockDim.x + threadIdx.x;
    if (e < N_EDGES) atomicAdd(&g_cnt[dst[e]], 1);
}

__global__ void k_scan1() {
    __shared__ int s[2][256];
    int b = blockIdx.x, t = threadIdx.x;
    int i = b * 256 + t;
    int v = (i < N_NODES) ? g_cnt[i] : 0;
    s[0][t] = v;
    __syncthreads();
    int p = 0;
#pragma unroll
    for (int off = 1; off < 256; off <<= 1) {
        int nv = s[p][t] + ((t >= off) ? s[p][t - off] : 0);
        s[p ^ 1][t] = nv;
        __syncthreads();
        p ^= 1;
    }
    if (i < N_NODES) g_off[i] = s[p][t] - v;
    if (t == 255) g_bsum[b] = s[p][255];
}

// scan2+scan3 fused: each block reduces bsum[0..b) itself.
__global__ void k_scan23() {
    __shared__ int red[256];
    int b = blockIdx.x, t = threadIdx.x;
    int v = (t < b) ? g_bsum[t] : 0;
    red[t] = v;
    __syncthreads();
#pragma unroll
    for (int off = 128; off; off >>= 1) {
        if (t < off) red[t] += red[t + off];
        __syncthreads();
    }
    int pre = red[0];
    int i = b * 256 + t;
    if (i < N_NODES) {
        int o = g_off[i] + pre;
        g_off[i] = o;
        g_cur[i] = o;
        g_inv[i] = 1.0f / fmaxf((float)g_cnt[i], 1.0f);
    }
    if (i == 0) g_off[N_NODES] = N_EDGES;
}

__global__ void k_fill(const int* __restrict__ src, const int* __restrict__ dst) {
    int e = blockIdx.x * blockDim.x + threadIdx.x;
    if (e < N_EDGES) {
        int pos = atomicAdd(&g_cur[dst[e]], 1);
        g_esrc[pos] = src[e];
    }
    int nt = gridDim.x * blockDim.x;
    for (int j = e; j < N_NODES; j += nt) g_cnt[j] = 0;
}

// ---------------------------------------------------------------------------
// Weight transpose to fp16: g_Wh[l][n][k] from
// Wcat[k][n] = (k<128 ? Wl[l][k][n] : Wr[l][k-128][n])
// ---------------------------------------------------------------------------
__global__ void k_wprep(const float* __restrict__ Wl, const float* __restrict__ Wr) {
    __shared__ float s[32][33];
    int K0 = blockIdx.x * 32;
    int N0 = blockIdx.y * 32;
    int l = blockIdx.z;
    int tx = threadIdx.x, ty = threadIdx.y;
    const float* WlL = Wl + l * HID * HID;
    const float* WrL = Wr + l * HID * HID;
#pragma unroll
    for (int i = 0; i < 4; i++) {
        int k = K0 + ty + i * 8;
        int n = N0 + tx;
        s[ty + i * 8][tx] = (k < HID) ? WlL[k * HID + n] : WrL[(k - HID) * HID + n];
    }
    __syncthreads();
    __half* O = g_Wh + (size_t)l * HID * 2 * HID;
#pragma unroll
    for (int i = 0; i < 4; i++) {
        int n = N0 + ty + i * 8;
        int k = K0 + tx;
        O[(size_t)n * 256 + k] = __float2half_rn(s[tx][ty + i * 8]);
    }
}

// ---------------------------------------------------------------------------
// h = x @ W_in + b_in    (50000 x 16 @ 16 x 128)
// ---------------------------------------------------------------------------
__global__ void k_in_gemm(const float* __restrict__ x,
                          const float* __restrict__ W,
                          const float* __restrict__ b) {
    __shared__ float xs[16][D_IN];
    __shared__ float Ws[D_IN][HID];
    int tid = threadIdx.x;
    int m0 = blockIdx.x * 16;

#pragma unroll
    for (int i = 0; i < 2; i++) {
        int idx = tid + i * 256;
        ((float4*)&Ws[0][0])[idx] = ((const float4*)W)[idx];
    }
    {
        int r = tid >> 4, k = tid & 15;
        xs[r][k] = x[(size_t)(m0 + r) * D_IN + k];
    }
    __syncthreads();

    int col = tid & 127;
    int rh  = tid >> 7;
    float wc[D_IN];
#pragma unroll
    for (int k = 0; k < D_IN; k++) wc[k] = Ws[k][col];
    float bb = b[col];

#pragma unroll
    for (int r = 0; r < 8; r++) {
        int row = rh * 8 + r;
        float acc = bb;
#pragma unroll
        for (int k = 0; k < D_IN; k++) acc += xs[row][k] * wc[k];
        g_h[(size_t)(m0 + row) * HID + col] = acc;
    }
}

// ---------------------------------------------------------------------------
// LayerNorm: hn = LN(h) * g + b, written fp16 only (gather + GEMM operand).
// One warp per row; lane handles a float4.
// ---------------------------------------------------------------------------
__global__ void k_ln(const float* __restrict__ g, const float* __restrict__ b) {
    int warp = (blockIdx.x * blockDim.x + threadIdx.x) >> 5;
    int lane = threadIdx.x & 31;
    if (warp >= N_NODES) return;

    float4 v = ((const float4*)(g_h + (size_t)warp * HID))[lane];
    float s = v.x + v.y + v.z + v.w;
#pragma unroll
    for (int o = 16; o; o >>= 1) s += __shfl_xor_sync(0xFFFFFFFFu, s, o);
    float mu = s * (1.0f / HID);

    float dx = v.x - mu, dy = v.y - mu, dz = v.z - mu, dw = v.w - mu;
    float q = dx * dx + dy * dy + dz * dz + dw * dw;
#pragma unroll
    for (int o = 16; o; o >>= 1) q += __shfl_xor_sync(0xFFFFFFFFu, q, o);
    float rs = rsqrtf(q * (1.0f / HID) + LN_EPS);

    int c = lane * 4;
    float4 gg = *(const float4*)(g + c);
    float4 bb = *(const float4*)(b + c);
    float ox = dx * rs * gg.x + bb.x;
    float oy = dy * rs * gg.y + bb.y;
    float oz = dz * rs * gg.z + bb.z;
    float ow = dw * rs * gg.w + bb.w;

    __half2 hh0 = __floats2half2_rn(ox, oy);
    __half2 hh1 = __floats2half2_rn(oz, ow);
    uint2 hp;
    hp.x = *(uint32_t*)&hh0;
    hp.y = *(uint32_t*)&hh1;
    ((uint2*)(g_hnh + (size_t)warp * HID))[lane] = hp;
}

// ---------------------------------------------------------------------------
// Aggregate (CSR): aggh[n] = fp16((sum of hn[src]) * inv_deg[n])
// Paired-edge gather: lanes 0-15 cover edge 2j (uint4 = full 256B row),
// lanes 16-31 cover edge 2j+1. Combine with shfl_xor(16) at the end.
// ---------------------------------------------------------------------------
__global__ void k_agg() {
    int node = (blockIdx.x * blockDim.x + threadIdx.x) >> 5;
    int lane = threadIdx.x & 31;
    if (node >= N_NODES) return;

    int half = lane >> 4;
    int hl = lane & 15;

    int beg = g_off[node];
    int end = g_off[node + 1];
    float4 a0 = make_float4(0.f, 0.f, 0.f, 0.f);
    float4 a1 = make_float4(0.f, 0.f, 0.f, 0.f);

    for (int e = beg; e < end; e += 32) {
        int rem = end - e;
        if (rem > 32) rem = 32;
        int sidx = (lane < rem) ? g_esrc[e + lane] : 0;
        int npair = rem >> 1;
#pragma unroll 4
        for (int j = 0; j < npair; j++) {
            int s = __shfl_sync(0xFFFFFFFFu, sidx, 2 * j + half);
            uint4 u = ((const uint4*)(g_hnh + (size_t)s * HID))[hl];
            float2 f;
            f = __half22float2(*(__half2*)&u.x); a0.x += f.x; a0.y += f.y;
            f = __half22float2(*(__half2*)&u.y); a0.z += f.x; a0.w += f.y;
            f = __half22float2(*(__half2*)&u.z); a1.x += f.x; a1.y += f.y;
            f = __half22float2(*(__half2*)&u.w); a1.z += f.x; a1.w += f.y;
        }
        if (rem & 1) {
            int s = __shfl_sync(0xFFFFFFFFu, sidx, rem - 1);
            if (half == 0) {
                uint4 u = ((const uint4*)(g_hnh + (size_t)s * HID))[hl];
                float2 f;
                f = __half22float2(*(__half2*)&u.x); a0.x += f.x; a0.y += f.y;
                f = __half22float2(*(__half2*)&u.y); a0.z += f.x; a0.w += f.y;
                f = __half22float2(*(__half2*)&u.z); a1.x += f.x; a1.y += f.y;
                f = __half22float2(*(__half2*)&u.w); a1.z += f.x; a1.w += f.y;
            }
        }
    }

    a0.x += __shfl_xor_sync(0xFFFFFFFFu, a0.x, 16);
    a0.y += __shfl_xor_sync(0xFFFFFFFFu, a0.y, 16);
    a0.z += __shfl_xor_sync(0xFFFFFFFFu, a0.z, 16);
    a0.w += __shfl_xor_sync(0xFFFFFFFFu, a0.w, 16);
    a1.x += __shfl_xor_sync(0xFFFFFFFFu, a1.x, 16);
    a1.y += __shfl_xor_sync(0xFFFFFFFFu, a1.y, 16);
    a1.z += __shfl_xor_sync(0xFFFFFFFFu, a1.z, 16);
    a1.w += __shfl_xor_sync(0xFFFFFFFFu, a1.w, 16);

    if (half == 0) {
        float inv = g_inv[node];
        __half2 h0 = __floats2half2_rn(a0.x * inv, a0.y * inv);
        __half2 h1 = __floats2half2_rn(a0.z * inv, a0.w * inv);
        __half2 h2 = __floats2half2_rn(a1.x * inv, a1.y * inv);
        __half2 h3 = __floats2half2_rn(a1.z * inv, a1.w * inv);
        uint4 o;
        o.x = *(uint32_t*)&h0; o.y = *(uint32_t*)&h1;
        o.z = *(uint32_t*)&h2; o.w = *(uint32_t*)&h3;
        ((uint4*)(g_aggh + (size_t)node * HID))[hl] = o;
    }
}

// ---------------------------------------------------------------------------
// Layer GEMM, all-fp16 single MMA:  h = relu(h + [aggh | hnh] @ Wh + bl)
// CTA tile 128x128, K=256 in 16 chunks of 16. 512 threads = 16 warps (4x4),
// warp tile 32x32 (2 m-frags x 4 n-frags), 1 MMA each per chunk.
// 2-stage smem double buffer, 48B pitch, pure-copy staging.
// ---------------------------------------------------------------------------
#define LPITCH 48
#define STG    6144          // 128 rows * 48B
#define LAYER_SMEM (4 * STG) // A0,B0,A1,B1 = 24576

__global__ void __launch_bounds__(512) k_layer(int l, const float* __restrict__ bl) {
    extern __shared__ char sm[];
    int tid = threadIdx.x;
    int lane = tid & 31, wid = tid >> 5;
    int wm = wid & 3, wn = wid >> 2;
    int m0 = blockIdx.x * 128;

    const __half* W_ = g_Wh + (size_t)l * HID * 2 * HID;

    float C[2][4][4];
#pragma unroll
    for (int mt = 0; mt < 2; mt++)
#pragma unroll
        for (int nt = 0; nt < 4; nt++)
#pragma unroll
            for (int j = 0; j < 4; j++) C[mt][nt][j] = 0.0f;

    int s_r = tid >> 2, s_q = tid & 3;   // row 0..127, 8B (4 halves) segment 0..3
    int arow = m0 + s_r;
    if (arow >= N_NODES) arow = N_NODES - 1;

    uint2 av, bv;
    av = *(const uint2*)(g_aggh + (size_t)arow * HID + s_q * 4);
    bv = *(const uint2*)(W_ + (size_t)s_r * 256 + s_q * 4);

    for (int c = 0; c < 16; c++) {
        int st = c & 1;
        char* As = sm + st * 2 * STG;
        char* Bs = As + STG;

        *(uint2*)(As + s_r * LPITCH + s_q * 8) = av;
        *(uint2*)(Bs + s_r * LPITCH + s_q * 8) = bv;
        __syncthreads();

        if (c < 15) {
            int cn = c + 1;
            const __half* Asrc = (cn < 8) ? (g_aggh + cn * 16) : (g_hnh + (cn - 8) * 16);
            av = *(const uint2*)(Asrc + (size_t)arow * HID + s_q * 4);
            bv = *(const uint2*)(W_ + (size_t)s_r * 256 + cn * 16 + s_q * 4);
        }

        uint32_t a[2][4], b[4][2];
#pragma unroll
        for (int mt = 0; mt < 2; mt++) {
            int off = (wm * 32 + mt * 16 + (lane >> 2)) * LPITCH + (lane & 3) * 4;
            a[mt][0] = *(uint32_t*)(As + off);
            a[mt][1] = *(uint32_t*)(As + off + 8 * LPITCH);
            a[mt][2] = *(uint32_t*)(As + off + 16);
            a[mt][3] = *(uint32_t*)(As + off + 8 * LPITCH + 16);
        }
#pragma unroll
        for (int nt = 0; nt < 4; nt++) {
            int off = (wn * 32 + nt * 8 + (lane >> 2)) * LPITCH + (lane & 3) * 4;
            b[nt][0] = *(uint32_t*)(Bs + off);
            b[nt][1] = *(uint32_t*)(Bs + off + 16);
        }

#pragma unroll
        for (int mt = 0; mt < 2; mt++)
#pragma unroll
            for (int nt = 0; nt < 4; nt++)
                mma_fp16(C[mt][nt], a[mt], b[nt]);
        __syncthreads();
    }

    // Epilogue: residual + bias + relu into g_h
#pragma unroll
    for (int mt = 0; mt < 2; mt++) {
        int r0 = m0 + wm * 32 + mt * 16 + (lane >> 2);
#pragma unroll
        for (int half = 0; half < 2; half++) {
            int r = r0 + half * 8;
            if (r < N_NODES) {
#pragma unroll
                for (int nt = 0; nt < 4; nt++) {
                    int cb = wn * 32 + nt * 8 + (lane & 3) * 2;
                    float* hp = g_h + (size_t)r * HID + cb;
                    float2 h2 = *(float2*)hp;
                    float2 bb = *(const float2*)(bl + cb);
                    float2 o;
                    o.x = fmaxf(h2.x + C[mt][nt][half * 2 + 0] + bb.x, 0.0f);
                    o.y = fmaxf(h2.y + C[mt][nt][half * 2 + 1] + bb.y, 0.0f);
                    *(float2*)hp = o;
                }
            }
        }
    }
}

// ---------------------------------------------------------------------------
// out = h @ W_out + b_out   (50000 x 128 @ 128 x 4), one warp per node
// ---------------------------------------------------------------------------
__global__ void k_out(const float* __restrict__ Wo,
                      const float* __restrict__ bo,
                      float* __restrict__ out) {
    __shared__ float Ws[HID * D_OUT];
    int tid = threadIdx.x;
    for (int i = tid; i < HID * D_OUT; i += blockDim.x) Ws[i] = Wo[i];
    __syncthreads();

    int warp = (blockIdx.x * blockDim.x + tid) >> 5;
    int lane = tid & 31;
    if (warp >= N_NODES) return;

    const float* hr = g_h + (size_t)warp * HID;
    float a0 = 0.f, a1 = 0.f, a2 = 0.f, a3 = 0.f;
#pragma unroll
    for (int t = 0; t < 4; t++) {
        int k = lane + t * 32;
        float hv = hr[k];
        a0 += hv * Ws[k * D_OUT + 0];
        a1 += hv * Ws[k * D_OUT + 1];
        a2 += hv * Ws[k * D_OUT + 2];
        a3 += hv * Ws[k * D_OUT + 3];
    }
#pragma unroll
    for (int o = 16; o; o >>= 1) {
        a0 += __shfl_xor_sync(0xFFFFFFFFu, a0, o);
        a1 += __shfl_xor_sync(0xFFFFFFFFu, a1, o);
        a2 += __shfl_xor_sync(0xFFFFFFFFu, a2, o);
        a3 += __shfl_xor_sync(0xFFFFFFFFu, a3, o);
    }
    if (lane == 0) {
        float4 r;
        r.x = a0 + bo[0];
        r.y = a1 + bo[1];
        r.z = a2 + bo[2];
        r.w = a3 + bo[3];
        *(float4*)(out + (size_t)warp * D_OUT) = r;
    }
}

// ---------------------------------------------------------------------------
// Launcher: two parallel graph branches.
//   branch A (stream 0): count -> scan1 -> scan23 -> fill        (CSR)
//   branch B (side str): wprep -> in_gemm -> ln(0)               (prep)
// Join, then the serial layer loop and output head on stream 0.
// Streams/events are host-side objects (no device memory); created per call.
// ---------------------------------------------------------------------------
extern "C" void kernel_launch(void* const* d_in, const int* in_sizes, int n_in,
                              void* d_out, int out_size) {
    const float* x     = (const float*)d_in[0];
    const int*   ei    = (const int*)  d_in[1];
    const float* W_in  = (const float*)d_in[2];
    const float* b_in  = (const float*)d_in[3];
    const float* Wl    = (const float*)d_in[4];
    const float* bl    = (const float*)d_in[5];
    const float* Wr    = (const float*)d_in[6];
    const float* ln_g  = (const float*)d_in[7];
    const float* ln_b  = (const float*)d_in[8];
    const float* W_out = (const float*)d_in[9];
    const float* b_out = (const float*)d_in[10];
    float* out = (float*)d_out;

    const int* src = ei;             // edge_index[0]
    const int* dst = ei + N_EDGES;   // edge_index[1]

    cudaFuncSetAttribute(k_layer, cudaFuncAttributeMaxDynamicSharedMemorySize, LAYER_SMEM);

    cudaStream_t s2;
    cudaStreamCreateWithFlags(&s2, cudaStreamNonBlocking);
    cudaEvent_t evFork, evJoin;
    cudaEventCreateWithFlags(&evFork, cudaEventDisableTiming);
    cudaEventCreateWithFlags(&evJoin, cudaEventDisableTiming);

    // Fork: side stream joins the capture of stream 0
    cudaEventRecord(evFork, 0);
    cudaStreamWaitEvent(s2, evFork, 0);

    // Branch A (stream 0): CSR build
    k_count<<<(N_EDGES + 255) / 256, 256>>>(dst);
    k_scan1<<<SCAN_BLOCKS, 256>>>();
    k_scan23<<<SCAN_BLOCKS, 256>>>();
    k_fill<<<(N_EDGES + 255) / 256, 256>>>(src, dst);

    // Branch B (s2): weight prep + input GEMM + LN(layer 0)
    {
        dim3 g(256 / 32, 128 / 32, N_LAYERS);
        dim3 b(32, 8);
        k_wprep<<<g, b, 0, s2>>>(Wl, Wr);
    }
    k_in_gemm<<<N_NODES / 16, 256, 0, s2>>>(x, W_in, b_in);
    k_ln<<<(N_NODES * 32 + 255) / 256, 256, 0, s2>>>(ln_g, ln_b);

    // Join branch B back into stream 0
    cudaEventRecord(evJoin, s2);
    cudaStreamWaitEvent(0, evJoin, 0);

    for (int l = 0; l < N_LAYERS; l++) {
        k_agg<<<(N_NODES * 32 + 255) / 256, 256>>>();
        k_layer<<<(N_NODES + 127) / 128, 512, LAYER_SMEM>>>(l, bl + l * HID);
        if (l + 1 < N_LAYERS)
            k_ln<<<(N_NODES * 32 + 255) / 256, 256>>>(ln_g + (l + 1) * HID,
                                                      ln_b + (l + 1) * HID);
    }

    k_out<<<(N_NODES * 32 + 255) / 256, 256>>>(W_out, b_out, out);
}

// round 16
// speedup vs baseline: 1.0818x; 1.0113x over previous
#include <cuda_runtime.h>
#include <cuda_fp16.h>
#include <cstdint>

#define N_NODES 50000
#define N_EDGES 800000
#define D_IN    16
#define HID     128
#define D_OUT   4
#define N_LAYERS 3
#define LN_EPS  1e-5f

#define SCAN_BLOCKS 196   // ceil(50000/256)

// Half-split for the per-layer pipeline (tile = 128 nodes; 391 tiles total)
#define TILES_TOTAL 391
#define TILES_H0    196
#define TILES_H1    (TILES_TOTAL - TILES_H0)      // 195
#define NODES_H0    (TILES_H0 * 128)              // 25088

// Scratch (device globals: allocation-free, graph-capturable).
// g_cnt relies on static zero-init for the first call; every call re-zeroes it
// at the end of k_fill, so all calls see zeros (deterministic across replays).
__device__ float  g_h   [N_NODES * HID];   // fp32 residual stream
__device__ __half g_hnh [N_NODES * HID];   // fp16 LN output
__device__ __half g_aggh[N_NODES * HID];   // fp16 aggregate
__device__ __half g_Wh  [N_LAYERS * HID * 2 * HID];  // [l][n=128][k=256] fp16
__device__ float g_inv [N_NODES];
__device__ int   g_cnt [N_NODES];
__device__ int   g_off [N_NODES + 1];
__device__ int   g_cur [N_NODES];
__device__ int   g_bsum[SCAN_BLOCKS];
__device__ int   g_esrc[N_EDGES];

// ---------------------------------------------------------------------------
// fp16 mma.sync (base PTX): D += A(16x16) * B(16x8), fp32 accum
// ---------------------------------------------------------------------------
__device__ __forceinline__ void mma_fp16(float* c, const uint32_t* a, const uint32_t* b) {
    asm volatile(
        "mma.sync.aligned.m16n8k16.row.col.f32.f16.f16.f32 "
        "{%0,%1,%2,%3}, {%4,%5,%6,%7}, {%8,%9}, {%0,%1,%2,%3};"
        : "+f"(c[0]), "+f"(c[1]), "+f"(c[2]), "+f"(c[3])
        : "r"(a[0]), "r"(a[1]), "r"(a[2]), "r"(a[3]), "r"(b[0]), "r"(b[1]));
}

// ---------------------------------------------------------------------------
// CSR build (4 launches): count -> scan1 -> scan23 -> fill(+rezero)
// ---------------------------------------------------------------------------
__global__ void k_count(const int* __restrict__ dst) {
    int e = blockIdx.x * blockDim.x + threadIdx.x;
    if (e < N_EDGES) atomicAdd(&g_cnt[dst[e]], 1);
}

__global__ void k_scan1() {
    __shared__ int s[2][256];
    int b = blockIdx.x, t = threadIdx.x;
    int i = b * 256 + t;
    int v = (i < N_NODES) ? g_cnt[i] : 0;
    s[0][t] = v;
    __syncthreads();
    int p = 0;
#pragma unroll
    for (int off = 1; off < 256; off <<= 1) {
        int nv = s[p][t] + ((t >= off) ? s[p][t - off] : 0);
        s[p ^ 1][t] = nv;
        __syncthreads();
        p ^= 1;
    }
    if (i < N_NODES) g_off[i] = s[p][t] - v;
    if (t == 255) g_bsum[b] = s[p][255];
}

// scan2+scan3 fused: each block reduces bsum[0..b) itself.
__global__ void k_scan23() {
    __shared__ int red[256];
    int b = blockIdx.x, t = threadIdx.x;
    int v = (t < b) ? g_bsum[t] : 0;
    red[t] = v;
    __syncthreads();
#pragma unroll
    for (int off = 128; off; off >>= 1) {
        if (t < off) red[t] += red[t + off];
        __syncthreads();
    }
    int pre = red[0];
    int i = b * 256 + t;
    if (i < N_NODES) {
        int o = g_off[i] + pre;
        g_off[i] = o;
        g_cur[i] = o;
        g_inv[i] = 1.0f / fmaxf((float)g_cnt[i], 1.0f);
    }
    if (i == 0) g_off[N_NODES] = N_EDGES;
}

__global__ void k_fill(const int* __restrict__ src, const int* __restrict__ dst) {
    int e = blockIdx.x * blockDim.x + threadIdx.x;
    if (e < N_EDGES) {
        int pos = atomicAdd(&g_cur[dst[e]], 1);
        g_esrc[pos] = src[e];
    }
    int nt = gridDim.x * blockDim.x;
    for (int j = e; j < N_NODES; j += nt) g_cnt[j] = 0;
}

// ---------------------------------------------------------------------------
// Weight transpose to fp16: g_Wh[l][n][k] from
// Wcat[k][n] = (k<128 ? Wl[l][k][n] : Wr[l][k-128][n])
// ---------------------------------------------------------------------------
__global__ void k_wprep(const float* __restrict__ Wl, const float* __restrict__ Wr) {
    __shared__ float s[32][33];
    int K0 = blockIdx.x * 32;
    int N0 = blockIdx.y * 32;
    int l = blockIdx.z;
    int tx = threadIdx.x, ty = threadIdx.y;
    const float* WlL = Wl + l * HID * HID;
    const float* WrL = Wr + l * HID * HID;
#pragma unroll
    for (int i = 0; i < 4; i++) {
        int k = K0 + ty + i * 8;
        int n = N0 + tx;
        s[ty + i * 8][tx] = (k < HID) ? WlL[k * HID + n] : WrL[(k - HID) * HID + n];
    }
    __syncthreads();
    __half* O = g_Wh + (size_t)l * HID * 2 * HID;
#pragma unroll
    for (int i = 0; i < 4; i++) {
        int n = N0 + ty + i * 8;
        int k = K0 + tx;
        O[(size_t)n * 256 + k] = __float2half_rn(s[tx][ty + i * 8]);
    }
}

// ---------------------------------------------------------------------------
// h = x @ W_in + b_in    (50000 x 16 @ 16 x 128)
// ---------------------------------------------------------------------------
__global__ void k_in_gemm(const float* __restrict__ x,
                          const float* __restrict__ W,
                          const float* __restrict__ b) {
    __shared__ float xs[16][D_IN];
    __shared__ float Ws[D_IN][HID];
    int tid = threadIdx.x;
    int m0 = blockIdx.x * 16;

#pragma unroll
    for (int i = 0; i < 2; i++) {
        int idx = tid + i * 256;
        ((float4*)&Ws[0][0])[idx] = ((const float4*)W)[idx];
    }
    {
        int r = tid >> 4, k = tid & 15;
        xs[r][k] = x[(size_t)(m0 + r) * D_IN + k];
    }
    __syncthreads();

    int col = tid & 127;
    int rh  = tid >> 7;
    float wc[D_IN];
#pragma unroll
    for (int k = 0; k < D_IN; k++) wc[k] = Ws[k][col];
    float bb = b[col];

#pragma unroll
    for (int r = 0; r < 8; r++) {
        int row = rh * 8 + r;
        float acc = bb;
#pragma unroll
        for (int k = 0; k < D_IN; k++) acc += xs[row][k] * wc[k];
        g_h[(size_t)(m0 + row) * HID + col] = acc;
    }
}

// ---------------------------------------------------------------------------
// LayerNorm: hn = LN(h) * g + b, written fp16 only. One warp per row.
// ---------------------------------------------------------------------------
__global__ void k_ln(const float* __restrict__ g, const float* __restrict__ b) {
    int warp = (blockIdx.x * blockDim.x + threadIdx.x) >> 5;
    int lane = threadIdx.x & 31;
    if (warp >= N_NODES) return;

    float4 v = ((const float4*)(g_h + (size_t)warp * HID))[lane];
    float s = v.x + v.y + v.z + v.w;
#pragma unroll
    for (int o = 16; o; o >>= 1) s += __shfl_xor_sync(0xFFFFFFFFu, s, o);
    float mu = s * (1.0f / HID);

    float dx = v.x - mu, dy = v.y - mu, dz = v.z - mu, dw = v.w - mu;
    float q = dx * dx + dy * dy + dz * dz + dw * dw;
#pragma unroll
    for (int o = 16; o; o >>= 1) q += __shfl_xor_sync(0xFFFFFFFFu, q, o);
    float rs = rsqrtf(q * (1.0f / HID) + LN_EPS);

    int c = lane * 4;
    float4 gg = *(const float4*)(g + c);
    float4 bb = *(const float4*)(b + c);
    float ox = dx * rs * gg.x + bb.x;
    float oy = dy * rs * gg.y + bb.y;
    float oz = dz * rs * gg.z + bb.z;
    float ow = dw * rs * gg.w + bb.w;

    __half2 hh0 = __floats2half2_rn(ox, oy);
    __half2 hh1 = __floats2half2_rn(oz, ow);
    uint2 hp;
    hp.x = *(uint32_t*)&hh0;
    hp.y = *(uint32_t*)&hh1;
    ((uint2*)(g_hnh + (size_t)warp * HID))[lane] = hp;
}

// ---------------------------------------------------------------------------
// Aggregate (CSR): aggh[n] = fp16((sum of hn[src]) * inv_deg[n])
// node = node0 + warp index. Paired-edge gather (lanes 0-15 edge 2j, lanes
// 16-31 edge 2j+1, uint4 = full 256B row), combine shfl_xor(16).
// ---------------------------------------------------------------------------
__global__ void k_agg(int node0, int node_end) {
    int node = node0 + ((blockIdx.x * blockDim.x + threadIdx.x) >> 5);
    int lane = threadIdx.x & 31;
    if (node >= node_end) return;

    int half = lane >> 4;
    int hl = lane & 15;

    int beg = g_off[node];
    int end = g_off[node + 1];
    float4 a0 = make_float4(0.f, 0.f, 0.f, 0.f);
    float4 a1 = make_float4(0.f, 0.f, 0.f, 0.f);

    for (int e = beg; e < end; e += 32) {
        int rem = end - e;
        if (rem > 32) rem = 32;
        int sidx = (lane < rem) ? g_esrc[e + lane] : 0;
        int npair = rem >> 1;
#pragma unroll 4
        for (int j = 0; j < npair; j++) {
            int s = __shfl_sync(0xFFFFFFFFu, sidx, 2 * j + half);
            uint4 u = ((const uint4*)(g_hnh + (size_t)s * HID))[hl];
            float2 f;
            f = __half22float2(*(__half2*)&u.x); a0.x += f.x; a0.y += f.y;
            f = __half22float2(*(__half2*)&u.y); a0.z += f.x; a0.w += f.y;
            f = __half22float2(*(__half2*)&u.z); a1.x += f.x; a1.y += f.y;
            f = __half22float2(*(__half2*)&u.w); a1.z += f.x; a1.w += f.y;
        }
        if (rem & 1) {
            int s = __shfl_sync(0xFFFFFFFFu, sidx, rem - 1);
            if (half == 0) {
                uint4 u = ((const uint4*)(g_hnh + (size_t)s * HID))[hl];
                float2 f;
                f = __half22float2(*(__half2*)&u.x); a0.x += f.x; a0.y += f.y;
                f = __half22float2(*(__half2*)&u.y); a0.z += f.x; a0.w += f.y;
                f = __half22float2(*(__half2*)&u.z); a1.x += f.x; a1.y += f.y;
                f = __half22float2(*(__half2*)&u.w); a1.z += f.x; a1.w += f.y;
            }
        }
    }

    a0.x += __shfl_xor_sync(0xFFFFFFFFu, a0.x, 16);
    a0.y += __shfl_xor_sync(0xFFFFFFFFu, a0.y, 16);
    a0.z += __shfl_xor_sync(0xFFFFFFFFu, a0.z, 16);
    a0.w += __shfl_xor_sync(0xFFFFFFFFu, a0.w, 16);
    a1.x += __shfl_xor_sync(0xFFFFFFFFu, a1.x, 16);
    a1.y += __shfl_xor_sync(0xFFFFFFFFu, a1.y, 16);
    a1.z += __shfl_xor_sync(0xFFFFFFFFu, a1.z, 16);
    a1.w += __shfl_xor_sync(0xFFFFFFFFu, a1.w, 16);

    if (half == 0) {
        float inv = g_inv[node];
        __half2 h0 = __floats2half2_rn(a0.x * inv, a0.y * inv);
        __half2 h1 = __floats2half2_rn(a0.z * inv, a0.w * inv);
        __half2 h2 = __floats2half2_rn(a1.x * inv, a1.y * inv);
        __half2 h3 = __floats2half2_rn(a1.z * inv, a1.w * inv);
        uint4 o;
        o.x = *(uint32_t*)&h0; o.y = *(uint32_t*)&h1;
        o.z = *(uint32_t*)&h2; o.w = *(uint32_t*)&h3;
        ((uint4*)(g_aggh + (size_t)node * HID))[hl] = o;
    }
}

// ---------------------------------------------------------------------------
// Layer GEMM, all-fp16 single MMA:  h = relu(h + [aggh | hnh] @ Wh + bl)
// Tile index = blockIdx.x + tile0 (for the half-split pipeline).
// CTA tile 128x128, K=256 in 16 chunks of 16. 512 threads = 16 warps (4x4),
// warp tile 32x32, 1 MMA each per chunk. 2-stage double buffer, 48B pitch.
// ---------------------------------------------------------------------------
#define LPITCH 48
#define STG    6144          // 128 rows * 48B
#define LAYER_SMEM (4 * STG) // A0,B0,A1,B1 = 24576

__global__ void __launch_bounds__(512) k_layer(int l, const float* __restrict__ bl,
                                               int tile0) {
    extern __shared__ char sm[];
    int tid = threadIdx.x;
    int lane = tid & 31, wid = tid >> 5;
    int wm = wid & 3, wn = wid >> 2;
    int m0 = (blockIdx.x + tile0) * 128;

    const __half* W_ = g_Wh + (size_t)l * HID * 2 * HID;

    float C[2][4][4];
#pragma unroll
    for (int mt = 0; mt < 2; mt++)
#pragma unroll
        for (int nt = 0; nt < 4; nt++)
#pragma unroll
            for (int j = 0; j < 4; j++) C[mt][nt][j] = 0.0f;

    int s_r = tid >> 2, s_q = tid & 3;
    int arow = m0 + s_r;
    if (arow >= N_NODES) arow = N_NODES - 1;

    uint2 av, bv;
    av = *(const uint2*)(g_aggh + (size_t)arow * HID + s_q * 4);
    bv = *(const uint2*)(W_ + (size_t)s_r * 256 + s_q * 4);

    for (int c = 0; c < 16; c++) {
        int st = c & 1;
        char* As = sm + st * 2 * STG;
        char* Bs = As + STG;

        *(uint2*)(As + s_r * LPITCH + s_q * 8) = av;
        *(uint2*)(Bs + s_r * LPITCH + s_q * 8) = bv;
        __syncthreads();

        if (c < 15) {
            int cn = c + 1;
            const __half* Asrc = (cn < 8) ? (g_aggh + cn * 16) : (g_hnh + (cn - 8) * 16);
            av = *(const uint2*)(Asrc + (size_t)arow * HID + s_q * 4);
            bv = *(const uint2*)(W_ + (size_t)s_r * 256 + cn * 16 + s_q * 4);
        }

        uint32_t a[2][4], b[4][2];
#pragma unroll
        for (int mt = 0; mt < 2; mt++) {
            int off = (wm * 32 + mt * 16 + (lane >> 2)) * LPITCH + (lane & 3) * 4;
            a[mt][0] = *(uint32_t*)(As + off);
            a[mt][1] = *(uint32_t*)(As + off + 8 * LPITCH);
            a[mt][2] = *(uint32_t*)(As + off + 16);
            a[mt][3] = *(uint32_t*)(As + off + 8 * LPITCH + 16);
        }
#pragma unroll
        for (int nt = 0; nt < 4; nt++) {
            int off = (wn * 32 + nt * 8 + (lane >> 2)) * LPITCH + (lane & 3) * 4;
            b[nt][0] = *(uint32_t*)(Bs + off);
            b[nt][1] = *(uint32_t*)(Bs + off + 16);
        }

#pragma unroll
        for (int mt = 0; mt < 2; mt++)
#pragma unroll
            for (int nt = 0; nt < 4; nt++)
                mma_fp16(C[mt][nt], a[mt], b[nt]);
        __syncthreads();
    }

    // Epilogue: residual + bias + relu into g_h
#pragma unroll
    for (int mt = 0; mt < 2; mt++) {
        int r0 = m0 + wm * 32 + mt * 16 + (lane >> 2);
#pragma unroll
        for (int half = 0; half < 2; half++) {
            int r = r0 + half * 8;
            if (r < N_NODES) {
#pragma unroll
                for (int nt = 0; nt < 4; nt++) {
                    int cb = wn * 32 + nt * 8 + (lane & 3) * 2;
                    float* hp = g_h + (size_t)r * HID + cb;
                    float2 h2 = *(float2*)hp;
                    float2 bb = *(const float2*)(bl + cb);
                    float2 o;
                    o.x = fmaxf(h2.x + C[mt][nt][half * 2 + 0] + bb.x, 0.0f);
                    o.y = fmaxf(h2.y + C[mt][nt][half * 2 + 1] + bb.y, 0.0f);
                    *(float2*)hp = o;
                }
            }
        }
    }
}

// ---------------------------------------------------------------------------
// out = h @ W_out + b_out   (50000 x 128 @ 128 x 4), one warp per node
// ---------------------------------------------------------------------------
__global__ void k_out(const float* __restrict__ Wo,
                      const float* __restrict__ bo,
                      float* __restrict__ out) {
    __shared__ float Ws[HID * D_OUT];
    int tid = threadIdx.x;
    for (int i = tid; i < HID * D_OUT; i += blockDim.x) Ws[i] = Wo[i];
    __syncthreads();

    int warp = (blockIdx.x * blockDim.x + tid) >> 5;
    int lane = tid & 31;
    if (warp >= N_NODES) return;

    const float* hr = g_h + (size_t)warp * HID;
    float a0 = 0.f, a1 = 0.f, a2 = 0.f, a3 = 0.f;
#pragma unroll
    for (int t = 0; t < 4; t++) {
        int k = lane + t * 32;
        float hv = hr[k];
        a0 += hv * Ws[k * D_OUT + 0];
        a1 += hv * Ws[k * D_OUT + 1];
        a2 += hv * Ws[k * D_OUT + 2];
        a3 += hv * Ws[k * D_OUT + 3];
    }
#pragma unroll
    for (int o = 16; o; o >>= 1) {
        a0 += __shfl_xor_sync(0xFFFFFFFFu, a0, o);
        a1 += __shfl_xor_sync(0xFFFFFFFFu, a1, o);
        a2 += __shfl_xor_sync(0xFFFFFFFFu, a2, o);
        a3 += __shfl_xor_sync(0xFFFFFFFFu, a3, o);
    }
    if (lane == 0) {
        float4 r;
        r.x = a0 + bo[0];
        r.y = a1 + bo[1];
        r.z = a2 + bo[2];
        r.w = a3 + bo[3];
        *(float4*)(out + (size_t)warp * D_OUT) = r;
    }
}

// ---------------------------------------------------------------------------
// Launcher (graph-parallel):
//   Setup fork:  A (s0): count->scan1->scan23->fill   B (s2): wprep->in_gemm->ln0
//   Per layer:   fork    s0: agg(H0)->layer(H0)       s2: agg(H1)->layer(H1)
//                join -> ln(l+1)
//   Then k_out.
// Streams/events are host-side objects (no device memory).
// ---------------------------------------------------------------------------
extern "C" void kernel_launch(void* const* d_in, const int* in_sizes, int n_in,
                              void* d_out, int out_size) {
    const float* x     = (const float*)d_in[0];
    const int*   ei    = (const int*)  d_in[1];
    const float* W_in  = (const float*)d_in[2];
    const float* b_in  = (const float*)d_in[3];
    const float* Wl    = (const float*)d_in[4];
    const float* bl    = (const float*)d_in[5];
    const float* Wr    = (const float*)d_in[6];
    const float* ln_g  = (const float*)d_in[7];
    const float* ln_b  = (const float*)d_in[8];
    const float* W_out = (const float*)d_in[9];
    const float* b_out = (const float*)d_in[10];
    float* out = (float*)d_out;

    const int* src = ei;             // edge_index[0]
    const int* dst = ei + N_EDGES;   // edge_index[1]

    cudaFuncSetAttribute(k_layer, cudaFuncAttributeMaxDynamicSharedMemorySize, LAYER_SMEM);

    cudaStream_t s2;
    cudaStreamCreateWithFlags(&s2, cudaStreamNonBlocking);

    auto fork = [&]() {
        cudaEvent_t ev;
        cudaEventCreateWithFlags(&ev, cudaEventDisableTiming);
        cudaEventRecord(ev, 0);
        cudaStreamWaitEvent(s2, ev, 0);
        cudaEventDestroy(ev);
    };
    auto join = [&]() {
        cudaEvent_t ev;
        cudaEventCreateWithFlags(&ev, cudaEventDisableTiming);
        cudaEventRecord(ev, s2);
        cudaStreamWaitEvent(0, ev, 0);
        cudaEventDestroy(ev);
    };

    // ---- Setup: CSR on s0, prep on s2 ----
    fork();
    k_count<<<(N_EDGES + 255) / 256, 256>>>(dst);
    k_scan1<<<SCAN_BLOCKS, 256>>>();
    k_scan23<<<SCAN_BLOCKS, 256>>>();
    k_fill<<<(N_EDGES + 255) / 256, 256>>>(src, dst);
    {
        dim3 g(256 / 32, 128 / 32, N_LAYERS);
        dim3 b(32, 8);
        k_wprep<<<g, b, 0, s2>>>(Wl, Wr);
    }
    k_in_gemm<<<N_NODES / 16, 256, 0, s2>>>(x, W_in, b_in);
    k_ln<<<(N_NODES * 32 + 255) / 256, 256, 0, s2>>>(ln_g, ln_b);
    join();

    // ---- Layers: half-split agg->layer chains on both streams ----
    const int aggBlocksH0 = (NODES_H0 * 32 + 255) / 256;
    const int aggBlocksH1 = ((N_NODES - NODES_H0) * 32 + 255) / 256;

    for (int l = 0; l < N_LAYERS; l++) {
        fork();
        // H0 on s0
        k_agg<<<aggBlocksH0, 256>>>(0, NODES_H0);
        k_layer<<<TILES_H0, 512, LAYER_SMEM>>>(l, bl + l * HID, 0);
        // H1 on s2
        k_agg<<<aggBlocksH1, 256, 0, s2>>>(NODES_H0, N_NODES);
        k_layer<<<TILES_H1, 512, LAYER_SMEM, s2>>>(l, bl + l * HID, TILES_H0);
        join();
        if (l + 1 < N_LAYERS)
            k_ln<<<(N_NODES * 32 + 255) / 256, 256>>>(ln_g + (l + 1) * HID,
                                                      ln_b + (l + 1) * HID);
    }

    k_out<<<(N_NODES * 32 + 255) / 256, 256>>>(W_out, b_out, out);
}

// round 17
// speedup vs baseline: 1.1209x; 1.0361x over previous
#include <cuda_runtime.h>
#include <cuda_fp16.h>
#include <cstdint>

#define N_NODES 50000
#define N_EDGES 800000
#define D_IN    16
#define HID     128
#define D_OUT   4
#define N_LAYERS 3
#define LN_EPS  1e-5f

#define SCAN_BLOCKS 196   // ceil(50000/256)

// Half-split for the per-layer pipeline (tile = 128 nodes; 391 tiles total)
#define TILES_TOTAL 391
#define TILES_H0    196
#define TILES_H1    (TILES_TOTAL - TILES_H0)      // 195
#define NODES_H0    (TILES_H0 * 128)              // 25088

// Scratch (device globals: allocation-free, graph-capturable).
// g_cnt relies on static zero-init for the first call; every call re-zeroes it
// at the end of k_fill, so all calls see zeros (deterministic across replays).
__device__ float  g_h   [N_NODES * HID];   // fp32 residual stream
__device__ __half g_hnh [N_NODES * HID];   // fp16 LN output
__device__ __half g_aggh[N_NODES * HID];   // fp16 aggregate
__device__ __half g_Wh  [N_LAYERS * HID * 2 * HID];  // [l][n=128][k=256] fp16
__device__ float g_inv [N_NODES];
__device__ int   g_cnt [N_NODES];
__device__ int   g_off [N_NODES + 1];
__device__ int   g_cur [N_NODES];
__device__ int   g_bsum[SCAN_BLOCKS];
__device__ int   g_esrc[N_EDGES];

// ---------------------------------------------------------------------------
// fp16 mma.sync (base PTX): D += A(16x16) * B(16x8), fp32 accum
// ---------------------------------------------------------------------------
__device__ __forceinline__ void mma_fp16(float* c, const uint32_t* a, const uint32_t* b) {
    asm volatile(
        "mma.sync.aligned.m16n8k16.row.col.f32.f16.f16.f32 "
        "{%0,%1,%2,%3}, {%4,%5,%6,%7}, {%8,%9}, {%0,%1,%2,%3};"
        : "+f"(c[0]), "+f"(c[1]), "+f"(c[2]), "+f"(c[3])
        : "r"(a[0]), "r"(a[1]), "r"(a[2]), "r"(a[3]), "r"(b[0]), "r"(b[1]));
}

// ---------------------------------------------------------------------------
// CSR build (4 launches): count -> scan1 -> scan23 -> fill(+rezero)
// ---------------------------------------------------------------------------
__global__ void k_count(const int* __restrict__ dst) {
    int e = blockIdx.x * blockDim.x + threadIdx.x;
    if (e < N_EDGES) atomicAdd(&g_cnt[dst[e]], 1);
}

__global__ void k_scan1() {
    __shared__ int s[2][256];
    int b = blockIdx.x, t = threadIdx.x;
    int i = b * 256 + t;
    int v = (i < N_NODES) ? g_cnt[i] : 0;
    s[0][t] = v;
    __syncthreads();
    int p = 0;
#pragma unroll
    for (int off = 1; off < 256; off <<= 1) {
        int nv = s[p][t] + ((t >= off) ? s[p][t - off] : 0);
        s[p ^ 1][t] = nv;
        __syncthreads();
        p ^= 1;
    }
    if (i < N_NODES) g_off[i] = s[p][t] - v;
    if (t == 255) g_bsum[b] = s[p][255];
}

// scan2+scan3 fused: each block reduces bsum[0..b) itself.
__global__ void k_scan23() {
    __shared__ int red[256];
    int b = blockIdx.x, t = threadIdx.x;
    int v = (t < b) ? g_bsum[t] : 0;
    red[t] = v;
    __syncthreads();
#pragma unroll
    for (int off = 128; off; off >>= 1) {
        if (t < off) red[t] += red[t + off];
        __syncthreads();
    }
    int pre = red[0];
    int i = b * 256 + t;
    if (i < N_NODES) {
        int o = g_off[i] + pre;
        g_off[i] = o;
        g_cur[i] = o;
        g_inv[i] = 1.0f / fmaxf((float)g_cnt[i], 1.0f);
    }
    if (i == 0) g_off[N_NODES] = N_EDGES;
}

__global__ void k_fill(const int* __restrict__ src, const int* __restrict__ dst) {
    int e = blockIdx.x * blockDim.x + threadIdx.x;
    if (e < N_EDGES) {
        int pos = atomicAdd(&g_cur[dst[e]], 1);
        g_esrc[pos] = src[e];
    }
    int nt = gridDim.x * blockDim.x;
    for (int j = e; j < N_NODES; j += nt) g_cnt[j] = 0;
}

// ---------------------------------------------------------------------------
// Weight transpose to fp16: g_Wh[l][n][k] from
// Wcat[k][n] = (k<128 ? Wl[l][k][n] : Wr[l][k-128][n])
// ---------------------------------------------------------------------------
__global__ void k_wprep(const float* __restrict__ Wl, const float* __restrict__ Wr) {
    __shared__ float s[32][33];
    int K0 = blockIdx.x * 32;
    int N0 = blockIdx.y * 32;
    int l = blockIdx.z;
    int tx = threadIdx.x, ty = threadIdx.y;
    const float* WlL = Wl + l * HID * HID;
    const float* WrL = Wr + l * HID * HID;
#pragma unroll
    for (int i = 0; i < 4; i++) {
        int k = K0 + ty + i * 8;
        int n = N0 + tx;
        s[ty + i * 8][tx] = (k < HID) ? WlL[k * HID + n] : WrL[(k - HID) * HID + n];
    }
    __syncthreads();
    __half* O = g_Wh + (size_t)l * HID * 2 * HID;
#pragma unroll
    for (int i = 0; i < 4; i++) {
        int n = N0 + ty + i * 8;
        int k = K0 + tx;
        O[(size_t)n * 256 + k] = __float2half_rn(s[tx][ty + i * 8]);
    }
}

// ---------------------------------------------------------------------------
// h = x @ W_in + b_in    (50000 x 16 @ 16 x 128)
// ---------------------------------------------------------------------------
__global__ void k_in_gemm(const float* __restrict__ x,
                          const float* __restrict__ W,
                          const float* __restrict__ b) {
    __shared__ float xs[16][D_IN];
    __shared__ float Ws[D_IN][HID];
    int tid = threadIdx.x;
    int m0 = blockIdx.x * 16;

#pragma unroll
    for (int i = 0; i < 2; i++) {
        int idx = tid + i * 256;
        ((float4*)&Ws[0][0])[idx] = ((const float4*)W)[idx];
    }
    {
        int r = tid >> 4, k = tid & 15;
        xs[r][k] = x[(size_t)(m0 + r) * D_IN + k];
    }
    __syncthreads();

    int col = tid & 127;
    int rh  = tid >> 7;
    float wc[D_IN];
#pragma unroll
    for (int k = 0; k < D_IN; k++) wc[k] = Ws[k][col];
    float bb = b[col];

#pragma unroll
    for (int r = 0; r < 8; r++) {
        int row = rh * 8 + r;
        float acc = bb;
#pragma unroll
        for (int k = 0; k < D_IN; k++) acc += xs[row][k] * wc[k];
        g_h[(size_t)(m0 + row) * HID + col] = acc;
    }
}

// ---------------------------------------------------------------------------
// LayerNorm over node range [node0, node_end): hn = LN(h) * g + b -> fp16.
// One warp per row.
// ---------------------------------------------------------------------------
__global__ void k_ln(const float* __restrict__ g, const float* __restrict__ b,
                     int node0, int node_end) {
    int warp = node0 + ((blockIdx.x * blockDim.x + threadIdx.x) >> 5);
    int lane = threadIdx.x & 31;
    if (warp >= node_end) return;

    float4 v = ((const float4*)(g_h + (size_t)warp * HID))[lane];
    float s = v.x + v.y + v.z + v.w;
#pragma unroll
    for (int o = 16; o; o >>= 1) s += __shfl_xor_sync(0xFFFFFFFFu, s, o);
    float mu = s * (1.0f / HID);

    float dx = v.x - mu, dy = v.y - mu, dz = v.z - mu, dw = v.w - mu;
    float q = dx * dx + dy * dy + dz * dz + dw * dw;
#pragma unroll
    for (int o = 16; o; o >>= 1) q += __shfl_xor_sync(0xFFFFFFFFu, q, o);
    float rs = rsqrtf(q * (1.0f / HID) + LN_EPS);

    int c = lane * 4;
    float4 gg = *(const float4*)(g + c);
    float4 bb = *(const float4*)(b + c);
    float ox = dx * rs * gg.x + bb.x;
    float oy = dy * rs * gg.y + bb.y;
    float oz = dz * rs * gg.z + bb.z;
    float ow = dw * rs * gg.w + bb.w;

    __half2 hh0 = __floats2half2_rn(ox, oy);
    __half2 hh1 = __floats2half2_rn(oz, ow);
    uint2 hp;
    hp.x = *(uint32_t*)&hh0;
    hp.y = *(uint32_t*)&hh1;
    ((uint2*)(g_hnh + (size_t)warp * HID))[lane] = hp;
}

// ---------------------------------------------------------------------------
// Aggregate (CSR): aggh[n] = fp16((sum of hn[src]) * inv_deg[n])
// node = node0 + warp index. Paired-edge gather (lanes 0-15 edge 2j, lanes
// 16-31 edge 2j+1, uint4 = full 256B row), combine shfl_xor(16).
// ---------------------------------------------------------------------------
__global__ void k_agg(int node0, int node_end) {
    int node = node0 + ((blockIdx.x * blockDim.x + threadIdx.x) >> 5);
    int lane = threadIdx.x & 31;
    if (node >= node_end) return;

    int half = lane >> 4;
    int hl = lane & 15;

    int beg = g_off[node];
    int end = g_off[node + 1];
    float4 a0 = make_float4(0.f, 0.f, 0.f, 0.f);
    float4 a1 = make_float4(0.f, 0.f, 0.f, 0.f);

    for (int e = beg; e < end; e += 32) {
        int rem = end - e;
        if (rem > 32) rem = 32;
        int sidx = (lane < rem) ? g_esrc[e + lane] : 0;
        int npair = rem >> 1;
#pragma unroll 4
        for (int j = 0; j < npair; j++) {
            int s = __shfl_sync(0xFFFFFFFFu, sidx, 2 * j + half);
            uint4 u = ((const uint4*)(g_hnh + (size_t)s * HID))[hl];
            float2 f;
            f = __half22float2(*(__half2*)&u.x); a0.x += f.x; a0.y += f.y;
            f = __half22float2(*(__half2*)&u.y); a0.z += f.x; a0.w += f.y;
            f = __half22float2(*(__half2*)&u.z); a1.x += f.x; a1.y += f.y;
            f = __half22float2(*(__half2*)&u.w); a1.z += f.x; a1.w += f.y;
        }
        if (rem & 1) {
            int s = __shfl_sync(0xFFFFFFFFu, sidx, rem - 1);
            if (half == 0) {
                uint4 u = ((const uint4*)(g_hnh + (size_t)s * HID))[hl];
                float2 f;
                f = __half22float2(*(__half2*)&u.x); a0.x += f.x; a0.y += f.y;
                f = __half22float2(*(__half2*)&u.y); a0.z += f.x; a0.w += f.y;
                f = __half22float2(*(__half2*)&u.z); a1.x += f.x; a1.y += f.y;
                f = __half22float2(*(__half2*)&u.w); a1.z += f.x; a1.w += f.y;
            }
        }
    }

    a0.x += __shfl_xor_sync(0xFFFFFFFFu, a0.x, 16);
    a0.y += __shfl_xor_sync(0xFFFFFFFFu, a0.y, 16);
    a0.z += __shfl_xor_sync(0xFFFFFFFFu, a0.z, 16);
    a0.w += __shfl_xor_sync(0xFFFFFFFFu, a0.w, 16);
    a1.x += __shfl_xor_sync(0xFFFFFFFFu, a1.x, 16);
    a1.y += __shfl_xor_sync(0xFFFFFFFFu, a1.y, 16);
    a1.z += __shfl_xor_sync(0xFFFFFFFFu, a1.z, 16);
    a1.w += __shfl_xor_sync(0xFFFFFFFFu, a1.w, 16);

    if (half == 0) {
        float inv = g_inv[node];
        __half2 h0 = __floats2half2_rn(a0.x * inv, a0.y * inv);
        __half2 h1 = __floats2half2_rn(a0.z * inv, a0.w * inv);
        __half2 h2 = __floats2half2_rn(a1.x * inv, a1.y * inv);
        __half2 h3 = __floats2half2_rn(a1.z * inv, a1.w * inv);
        uint4 o;
        o.x = *(uint32_t*)&h0; o.y = *(uint32_t*)&h1;
        o.z = *(uint32_t*)&h2; o.w = *(uint32_t*)&h3;
        ((uint4*)(g_aggh + (size_t)node * HID))[hl] = o;
    }
}

// ---------------------------------------------------------------------------
// Layer GEMM, all-fp16 single MMA:  h = relu(h + [aggh | hnh] @ Wh + bl)
// Tile index = blockIdx.x + tile0 (for the half-split pipeline).
// CTA tile 128x128, K=256 in 16 chunks of 16. 512 threads = 16 warps (4x4),
// warp tile 32x32, 1 MMA each per chunk. 2-stage double buffer, 48B pitch.
// ---------------------------------------------------------------------------
#define LPITCH 48
#define STG    6144          // 128 rows * 48B
#define LAYER_SMEM (4 * STG) // A0,B0,A1,B1 = 24576

__global__ void __launch_bounds__(512) k_layer(int l, const float* __restrict__ bl,
                                               int tile0) {
    extern __shared__ char sm[];
    int tid = threadIdx.x;
    int lane = tid & 31, wid = tid >> 5;
    int wm = wid & 3, wn = wid >> 2;
    int m0 = (blockIdx.x + tile0) * 128;

    const __half* W_ = g_Wh + (size_t)l * HID * 2 * HID;

    float C[2][4][4];
#pragma unroll
    for (int mt = 0; mt < 2; mt++)
#pragma unroll
        for (int nt = 0; nt < 4; nt++)
#pragma unroll
            for (int j = 0; j < 4; j++) C[mt][nt][j] = 0.0f;

    int s_r = tid >> 2, s_q = tid & 3;
    int arow = m0 + s_r;
    if (arow >= N_NODES) arow = N_NODES - 1;

    uint2 av, bv;
    av = *(const uint2*)(g_aggh + (size_t)arow * HID + s_q * 4);
    bv = *(const uint2*)(W_ + (size_t)s_r * 256 + s_q * 4);

    for (int c = 0; c < 16; c++) {
        int st = c & 1;
        char* As = sm + st * 2 * STG;
        char* Bs = As + STG;

        *(uint2*)(As + s_r * LPITCH + s_q * 8) = av;
        *(uint2*)(Bs + s_r * LPITCH + s_q * 8) = bv;
        __syncthreads();

        if (c < 15) {
            int cn = c + 1;
            const __half* Asrc = (cn < 8) ? (g_aggh + cn * 16) : (g_hnh + (cn - 8) * 16);
            av = *(const uint2*)(Asrc + (size_t)arow * HID + s_q * 4);
            bv = *(const uint2*)(W_ + (size_t)s_r * 256 + cn * 16 + s_q * 4);
        }

        uint32_t a[2][4], b[4][2];
#pragma unroll
        for (int mt = 0; mt < 2; mt++) {
            int off = (wm * 32 + mt * 16 + (lane >> 2)) * LPITCH + (lane & 3) * 4;
            a[mt][0] = *(uint32_t*)(As + off);
            a[mt][1] = *(uint32_t*)(As + off + 8 * LPITCH);
            a[mt][2] = *(uint32_t*)(As + off + 16);
            a[mt][3] = *(uint32_t*)(As + off + 8 * LPITCH + 16);
        }
#pragma unroll
        for (int nt = 0; nt < 4; nt++) {
            int off = (wn * 32 + nt * 8 + (lane >> 2)) * LPITCH + (lane & 3) * 4;
            b[nt][0] = *(uint32_t*)(Bs + off);
            b[nt][1] = *(uint32_t*)(Bs + off + 16);
        }

#pragma unroll
        for (int mt = 0; mt < 2; mt++)
#pragma unroll
            for (int nt = 0; nt < 4; nt++)
                mma_fp16(C[mt][nt], a[mt], b[nt]);
        __syncthreads();
    }

    // Epilogue: residual + bias + relu into g_h
#pragma unroll
    for (int mt = 0; mt < 2; mt++) {
        int r0 = m0 + wm * 32 + mt * 16 + (lane >> 2);
#pragma unroll
        for (int half = 0; half < 2; half++) {
            int r = r0 + half * 8;
            if (r < N_NODES) {
#pragma unroll
                for (int nt = 0; nt < 4; nt++) {
                    int cb = wn * 32 + nt * 8 + (lane & 3) * 2;
                    float* hp = g_h + (size_t)r * HID + cb;
                    float2 h2 = *(float2*)hp;
                    float2 bb = *(const float2*)(bl + cb);
                    float2 o;
                    o.x = fmaxf(h2.x + C[mt][nt][half * 2 + 0] + bb.x, 0.0f);
                    o.y = fmaxf(h2.y + C[mt][nt][half * 2 + 1] + bb.y, 0.0f);
                    *(float2*)hp = o;
                }
            }
        }
    }
}

// ---------------------------------------------------------------------------
// out = h @ W_out + b_out over node range [node0, node_end). One warp/node.
// ---------------------------------------------------------------------------
__global__ void k_out(const float* __restrict__ Wo,
                      const float* __restrict__ bo,
                      float* __restrict__ out, int node0, int node_end) {
    __shared__ float Ws[HID * D_OUT];
    int tid = threadIdx.x;
    for (int i = tid; i < HID * D_OUT; i += blockDim.x) Ws[i] = Wo[i];
    __syncthreads();

    int warp = node0 + ((blockIdx.x * blockDim.x + tid) >> 5);
    int lane = tid & 31;
    if (warp >= node_end) return;

    const float* hr = g_h + (size_t)warp * HID;
    float a0 = 0.f, a1 = 0.f, a2 = 0.f, a3 = 0.f;
#pragma unroll
    for (int t = 0; t < 4; t++) {
        int k = lane + t * 32;
        float hv = hr[k];
        a0 += hv * Ws[k * D_OUT + 0];
        a1 += hv * Ws[k * D_OUT + 1];
        a2 += hv * Ws[k * D_OUT + 2];
        a3 += hv * Ws[k * D_OUT + 3];
    }
#pragma unroll
    for (int o = 16; o; o >>= 1) {
        a0 += __shfl_xor_sync(0xFFFFFFFFu, a0, o);
        a1 += __shfl_xor_sync(0xFFFFFFFFu, a1, o);
        a2 += __shfl_xor_sync(0xFFFFFFFFu, a2, o);
        a3 += __shfl_xor_sync(0xFFFFFFFFu, a3, o);
    }
    if (lane == 0) {
        float4 r;
        r.x = a0 + bo[0];
        r.y = a1 + bo[1];
        r.z = a2 + bo[2];
        r.w = a3 + bo[3];
        *(float4*)(out + (size_t)warp * D_OUT) = r;
    }
}

// ---------------------------------------------------------------------------
// Launcher (graph-parallel):
//   Setup fork:  s0: count->scan1->scan23->fill   s2: wprep->in_gemm->ln0
//   Per layer l: fork; s0: agg(H0)->layer(H0)->[ln(H0)|out(H0)]
//                      s2: agg(H1)->layer(H1)->[ln(H1)|out(H1)]; join
//   (ln inside halves since LN is row-local; join only needed before agg.)
// Streams/events are host-side objects (no device memory).
// ---------------------------------------------------------------------------
extern "C" void kernel_launch(void* const* d_in, const int* in_sizes, int n_in,
                              void* d_out, int out_size) {
    const float* x     = (const float*)d_in[0];
    const int*   ei    = (const int*)  d_in[1];
    const float* W_in  = (const float*)d_in[2];
    const float* b_in  = (const float*)d_in[3];
    const float* Wl    = (const float*)d_in[4];
    const float* bl    = (const float*)d_in[5];
    const float* Wr    = (const float*)d_in[6];
    const float* ln_g  = (const float*)d_in[7];
    const float* ln_b  = (const float*)d_in[8];
    const float* W_out = (const float*)d_in[9];
    const float* b_out = (const float*)d_in[10];
    float* out = (float*)d_out;

    const int* src = ei;             // edge_index[0]
    const int* dst = ei + N_EDGES;   // edge_index[1]

    cudaFuncSetAttribute(k_layer, cudaFuncAttributeMaxDynamicSharedMemorySize, LAYER_SMEM);

    cudaStream_t s2;
    cudaStreamCreateWithFlags(&s2, cudaStreamNonBlocking);

    auto fork = [&]() {
        cudaEvent_t ev;
        cudaEventCreateWithFlags(&ev, cudaEventDisableTiming);
        cudaEventRecord(ev, 0);
        cudaStreamWaitEvent(s2, ev, 0);
        cudaEventDestroy(ev);
    };
    auto join = [&]() {
        cudaEvent_t ev;
        cudaEventCreateWithFlags(&ev, cudaEventDisableTiming);
        cudaEventRecord(ev, s2);
        cudaStreamWaitEvent(0, ev, 0);
        cudaEventDestroy(ev);
    };

    // ---- Setup: CSR on s0, prep + LN0 on s2 ----
    fork();
    k_count<<<(N_EDGES + 255) / 256, 256>>>(dst);
    k_scan1<<<SCAN_BLOCKS, 256>>>();
    k_scan23<<<SCAN_BLOCKS, 256>>>();
    k_fill<<<(N_EDGES + 255) / 256, 256>>>(src, dst);
    {
        dim3 g(256 / 32, 128 / 32, N_LAYERS);
        dim3 b(32, 8);
        k_wprep<<<g, b, 0, s2>>>(Wl, Wr);
    }
    k_in_gemm<<<N_NODES / 16, 256, 0, s2>>>(x, W_in, b_in);
    k_ln<<<(N_NODES * 32 + 255) / 256, 256, 0, s2>>>(ln_g, ln_b, 0, N_NODES);
    join();

    // ---- Layers: half-split agg->layer->ln chains on both streams ----
    const int aggBlocksH0 = (NODES_H0 * 32 + 255) / 256;
    const int aggBlocksH1 = ((N_NODES - NODES_H0) * 32 + 255) / 256;
    const int lnBlocksH0  = aggBlocksH0;
    const int lnBlocksH1  = aggBlocksH1;

    for (int l = 0; l < N_LAYERS; l++) {
        bool last = (l + 1 == N_LAYERS);
        fork();
        // H0 on s0
        k_agg<<<aggBlocksH0, 256>>>(0, NODES_H0);
        k_layer<<<TILES_H0, 512, LAYER_SMEM>>>(l, bl + l * HID, 0);
        if (!last)
            k_ln<<<lnBlocksH0, 256>>>(ln_g + (l + 1) * HID, ln_b + (l + 1) * HID,
                                      0, NODES_H0);
        else
            k_out<<<lnBlocksH0, 256>>>(W_out, b_out, out, 0, NODES_H0);
        // H1 on s2
        k_agg<<<aggBlocksH1, 256, 0, s2>>>(NODES_H0, N_NODES);
        k_layer<<<TILES_H1, 512, LAYER_SMEM, s2>>>(l, bl + l * HID, TILES_H0);
        if (!last)
            k_ln<<<lnBlocksH1, 256, 0, s2>>>(ln_g + (l + 1) * HID, ln_b + (l + 1) * HID,
                                             NODES_H0, N_NODES);
        else
            k_out<<<lnBlocksH1, 256, 0, s2>>>(W_out, b_out, out, NODES_H0, N_NODES);
        join();
    }
}